// round 5
// baseline (speedup 1.0000x reference)
#include <cuda_runtime.h>
#include <cuda_bf16.h>
#include <cstdint>

#define BB 8
#define SS 4096
#define HH 1024
#define KK 2048   // K = 0.5 * S

__device__ float g_logits[BB * SS];
__device__ int   g_hist[BB * 256];   // zero-initialized at load; re-zeroed by topk each call

__device__ __forceinline__ uint32_t orderable(float f) {
    uint32_t u = __float_as_uint(f);
    return u ^ ((u >> 31) ? 0xFFFFFFFFu : 0x80000000u);
}

// ---------------------------------------------------------------------------
// Pass 1: router GEMV, 2 tokens/warp. Also builds the top-byte histogram
// (radix pass 0) via global REDG atomics — hidden under the DRAM-bound loop.
// ---------------------------------------------------------------------------
__global__ __launch_bounds__(256) void router_logits_kernel(
    const float* __restrict__ x, const float* __restrict__ w,
    float* __restrict__ logits, int* __restrict__ hist_g)
{
    int gw   = (blockIdx.x * blockDim.x + threadIdx.x) >> 5;
    int lane = threadIdx.x & 31;
    int r0   = gw * 2;
    if (r0 >= BB * SS) return;

    const float4* xp0 = reinterpret_cast<const float4*>(x + (size_t)r0 * HH);
    const float4* xp1 = xp0 + (HH / 4);
    const float4* wp  = reinterpret_cast<const float4*>(w);

    float a0 = 0.0f, a1 = 0.0f;
#pragma unroll
    for (int i = 0; i < 8; i++) {                 // 8 * 32 * 4 = 1024 = H
        int idx = lane + i * 32;
        float4 wv = __ldg(&wp[idx]);
        float4 u  = xp0[idx];
        float4 t  = xp1[idx];
        a0 = fmaf(u.x, wv.x, a0); a0 = fmaf(u.y, wv.y, a0);
        a0 = fmaf(u.z, wv.z, a0); a0 = fmaf(u.w, wv.w, a0);
        a1 = fmaf(t.x, wv.x, a1); a1 = fmaf(t.y, wv.y, a1);
        a1 = fmaf(t.z, wv.z, a1); a1 = fmaf(t.w, wv.w, a1);
    }
#pragma unroll
    for (int o = 16; o; o >>= 1) {
        a0 += __shfl_xor_sync(0xFFFFFFFFu, a0, o);
        a1 += __shfl_xor_sync(0xFFFFFFFFu, a1, o);
    }
    if (lane == 0) {
        logits[r0]     = a0;
        logits[r0 + 1] = a1;
        const int b = r0 >> 12;            // r0 / SS
        int* hrow = hist_g + b * 256;
        atomicAdd(&hrow[orderable(a0) >> 24], 1);   // radix pass-0 bins
        atomicAdd(&hrow[orderable(a1) >> 24], 1);
    }
}

// ---------------------------------------------------------------------------
// Pass 2: per-row exact top-K. Pass 0 comes precomputed from g_hist;
// passes 1-3 only touch elements matching the prefix (~hundreds).
// 1024 threads, 4 consecutive elements/thread, float4 I/O.
// ---------------------------------------------------------------------------
__global__ __launch_bounds__(1024) void topk_select_kernel(
    const float* __restrict__ logits, int* __restrict__ hist_g,
    float* __restrict__ out, int out_size)
{
    __shared__ uint32_t skeys[SS];   // for the rare tie path only
    __shared__ int      hist[256];
    __shared__ uint32_t sh_prefix;
    __shared__ int      sh_kk;
    __shared__ int      sh_E;
    __shared__ int      sh_cut;

    const int b   = blockIdx.x;
    const int tid = threadIdx.x;
    const float* row = logits + b * SS;

    // Vectorized load of 4 consecutive logits per thread
    float4 lv = *reinterpret_cast<const float4*>(row + tid * 4);
    float    v[4] = {lv.x, lv.y, lv.z, lv.w};
    uint32_t k[4];
#pragma unroll
    for (int i = 0; i < 4; i++) {
        k[i] = orderable(v[i]);
        skeys[tid * 4 + i] = k[i];
    }

    // ---- Radix pass 0: scan the precomputed global histogram ----
    if (tid < 32) {
        const int* gh = hist_g + b * 256;
        const int lane = tid;
        int h[8];
        int part = 0;
#pragma unroll
        for (int j = 0; j < 8; j++) {
            h[j] = gh[255 - (lane * 8 + j)];
            part += h[j];
        }
        int inc = part;
#pragma unroll
        for (int o = 1; o < 32; o <<= 1) {
            int t = __shfl_up_sync(0xFFFFFFFFu, inc, o);
            if (lane >= o) inc += t;
        }
        const int excl = inc - part;
        if (excl < KK && excl + part >= KK) {
            int acc = excl;
#pragma unroll
            for (int j = 0; j < 8; j++) {
                if (acc + h[j] >= KK) {
                    int d = 255 - (lane * 8 + j);
                    sh_prefix = (uint32_t)d << 24;
                    sh_kk = KK - acc;
                    sh_E  = h[j];
                    break;
                }
                acc += h[j];
            }
        }
    }
    __syncthreads();
    // Re-zero the global histogram for the next call (deterministic state)
    if (tid < 256) hist_g[b * 256 + tid] = 0;

    // ---- Radix passes 1-3 on elements matching the prefix ----
#pragma unroll
    for (int pass = 0; pass < 3; pass++) {
        const int shift = 16 - pass * 8;
        const uint32_t pmask = 0xFFFFFFFFu << (shift + 8);

        if (tid < 256) hist[tid] = 0;
        __syncthreads();

        const uint32_t prefix = sh_prefix;
#pragma unroll
        for (int i = 0; i < 4; i++)
            if ((k[i] & pmask) == prefix)
                atomicAdd(&hist[(k[i] >> shift) & 0xFF], 1);
        __syncthreads();

        if (tid < 32) {
            const int kk   = sh_kk;
            const int lane = tid;
            int h[8];
            int part = 0;
#pragma unroll
            for (int j = 0; j < 8; j++) {
                h[j] = hist[255 - (lane * 8 + j)];
                part += h[j];
            }
            int inc = part;
#pragma unroll
            for (int o = 1; o < 32; o <<= 1) {
                int t = __shfl_up_sync(0xFFFFFFFFu, inc, o);
                if (lane >= o) inc += t;
            }
            const int excl = inc - part;
            if (excl < kk && excl + part >= kk) {
                int acc = excl;
#pragma unroll
                for (int j = 0; j < 8; j++) {
                    if (acc + h[j] >= kk) {
                        int d = 255 - (lane * 8 + j);
                        sh_prefix = prefix | ((uint32_t)d << shift);
                        sh_kk = kk - acc;
                        sh_E  = h[j];
                        break;
                    }
                    acc += h[j];
                }
            }
        }
        __syncthreads();
    }

    const uint32_t thresh = sh_prefix;  // exact K-th largest key
    const int T = sh_kk;
    const int E = sh_E;

    if (tid == 0) {
        if (E > T) {
            // rare tie path: first T equals by index (lax.top_k stability)
            int taken = 0, cut = -1;
            for (int s = 0; s < SS; s++) {
                if (skeys[s] == thresh) {
                    if (++taken == T) { cut = s; break; }
                }
            }
            sh_cut = cut;
        } else {
            sh_cut = SS;
        }
    }
    __syncthreads();
    const int cut = sh_cut;

    // ---- Emit: float4 stores ----
    const int  base = b * SS;
    const bool has_mask_half = (out_size >= 2 * BB * SS);
    float wv4[4], mv4[4];
#pragma unroll
    for (int i = 0; i < 4; i++) {
        int s = tid * 4 + i;
        bool m = (k[i] > thresh) || (k[i] == thresh && s <= cut);
        float score = 1.0f / (1.0f + expf(-v[i]));
        wv4[i] = m ? score : 0.0f;
        mv4[i] = m ? 1.0f : 0.0f;
    }
    *reinterpret_cast<float4*>(out + base + tid * 4) =
        make_float4(wv4[0], wv4[1], wv4[2], wv4[3]);
    if (has_mask_half)
        *reinterpret_cast<float4*>(out + BB * SS + base + tid * 4) =
            make_float4(mv4[0], mv4[1], mv4[2], mv4[3]);
}

extern "C" void kernel_launch(void* const* d_in, const int* in_sizes, int n_in,
                              void* d_out, int out_size)
{
    const float* hidden = (const float*)d_in[0];
    const float* w      = (const float*)d_in[1];
    float* out = (float*)d_out;

    float* logits = nullptr;
    int*   hist   = nullptr;
    cudaGetSymbolAddress((void**)&logits, g_logits);
    cudaGetSymbolAddress((void**)&hist,   g_hist);

    const int tokens = BB * SS;
    router_logits_kernel<<<tokens / 16, 256>>>(hidden, w, logits, hist);
    topk_select_kernel<<<BB, 1024>>>(logits, hist, out, out_size);
}